// round 14
// baseline (speedup 1.0000x reference)
#include <cuda_runtime.h>
#include <cuda_fp16.h>
#include <cstdint>

#define NROWS 16384
#define NCODE 8192
#define DDIM  512
#define NTILE 128
#define NTILES (NCODE / NTILE)   /* 64 */

__device__ __half g_xh[(size_t)NROWS * DDIM];
__device__ __half g_eh[(size_t)NCODE * DDIM];
__device__ unsigned g_tmax[(size_t)NROWS * NTILES];   // order-mapped floats; 0 = identity

// ---------------- helpers ----------------
static __device__ __forceinline__ uint32_t smem_u32(const void* p) {
    uint32_t a;
    asm("{ .reg .u64 t; cvta.to.shared.u64 t, %1; cvt.u32.u64 %0, t; }" : "=r"(a) : "l"(p));
    return a;
}
static __device__ __forceinline__ void cp16(uint32_t dst, const void* src) {
    asm volatile("cp.async.cg.shared.global [%0], [%1], 16;"
                 :: "r"(dst), "l"(__cvta_generic_to_global(src)));
}
static __device__ __forceinline__ void ldsm_x4(uint32_t* r, uint32_t addr) {
    asm volatile("ldmatrix.sync.aligned.m8n8.x4.shared.b16 {%0,%1,%2,%3}, [%4];"
                 : "=r"(r[0]), "=r"(r[1]), "=r"(r[2]), "=r"(r[3]) : "r"(addr));
}
static __device__ __forceinline__ void mma16816h(uint32_t* d, const uint32_t* a, const uint32_t* b) {
    asm volatile(
        "mma.sync.aligned.m16n8k16.row.col.f16.f16.f16.f16 "
        "{%0,%1},{%2,%3,%4,%5},{%6,%7},{%0,%1};"
        : "+r"(d[0]), "+r"(d[1])
        : "r"(a[0]), "r"(a[1]), "r"(a[2]), "r"(a[3]), "r"(b[0]), "r"(b[1]));
}
static __device__ __forceinline__ unsigned fmap(float v) {
    int i = __float_as_int(v);
    return (unsigned)i ^ (unsigned)((i >> 31) | 0x80000000);
}
static __device__ __forceinline__ float funmap(unsigned k) {
    int i = (k & 0x80000000u) ? (int)(k ^ 0x80000000u) : (int)~k;
    return __int_as_float(i);
}

// ---------------- normalize rows -> f16 (+ clear g_tmax) ----------------
__global__ __launch_bounds__(128) void k_norm(const float* __restrict__ x,
                                              const float* __restrict__ e) {
    const int b = blockIdx.x, tid = threadIdx.x;
    const float* in;
    __half* out;
    if (b < NROWS) {
        in = x + (size_t)b * DDIM; out = g_xh + (size_t)b * DDIM;
        if (tid < NTILES) g_tmax[(size_t)b * NTILES + tid] = 0u;
    } else {
        in = e + (size_t)(b - NROWS) * DDIM; out = g_eh + (size_t)(b - NROWS) * DDIM;
    }
    const float4 v = ((const float4*)in)[tid];
    float ss = v.x * v.x + v.y * v.y + v.z * v.z + v.w * v.w;
    #pragma unroll
    for (int o = 16; o; o >>= 1) ss += __shfl_down_sync(0xffffffffu, ss, o);
    __shared__ float sred[4];
    if ((tid & 31) == 0) sred[tid >> 5] = ss;
    __syncthreads();
    if (tid == 0) {
        float t = sred[0] + sred[1] + sred[2] + sred[3];
        sred[0] = 1.0f / fmaxf(sqrtf(t), 1e-12f);
    }
    __syncthreads();
    const float sc = sred[0];
    __half2* oh = (__half2*)out;
    oh[tid * 2]     = __floats2half2_rn(v.x * sc, v.y * sc);
    oh[tid * 2 + 1] = __floats2half2_rn(v.z * sc, v.w * sc);
}

// ---------------- mma.sync GEMM (f16 acc): KC=32, 4 stages, wait_group 2 ----
// CTA 128x128, 128 threads (2x2 warps, warp 64x64), 3 CTAs/SM, reg dbuf.
#define KC 32
#define NCHUNK (DDIM / KC)              /* 16 */
#define T_BYTES (128 * 64)              /* one operand per stage: 8 KB */
#define STG_BYTES (2 * T_BYTES)         /* 16 KB */
#define GEMM_SMEM (4 * STG_BYTES)       /* 64 KB */

static __device__ __forceinline__ void load_chunk(uint32_t abase, uint32_t bbase,
                                                  int m0, int n0, int k0, int tid) {
    #pragma unroll
    for (int i = 0; i < 4; i++) {
        int idx = tid + (i << 7);
        int row = idx >> 2, g = idx & 3;
        uint32_t dst = (uint32_t)(row * 64) + ((uint32_t)(g ^ (row & 3)) << 4);
        cp16(abase + dst, g_xh + (size_t)(m0 + row) * DDIM + k0 + g * 8);
        cp16(bbase + dst, g_eh + (size_t)(n0 + row) * DDIM + k0 + g * 8);
    }
    asm volatile("cp.async.commit_group;" ::: "memory");
}

static __device__ __forceinline__ void load_frags(
    uint32_t abase, uint32_t bbase, int ks,
    uint32_t af[4][4], uint32_t bf[8][2],
    int a_row, int a_hi, int b_row, int b_hi) {
    #pragma unroll
    for (int im = 0; im < 4; im++) {
        int row = a_row + im * 16;
        uint32_t col = (uint32_t)((ks * 2 + a_hi) ^ (row & 3)) << 4;
        ldsm_x4(af[im], abase + row * 64 + col);
    }
    #pragma unroll
    for (int ng = 0; ng < 4; ng++) {
        int row = b_row + ng * 16;
        uint32_t col = (uint32_t)((ks * 2 + b_hi) ^ (row & 3)) << 4;
        uint32_t t[4];
        ldsm_x4(t, bbase + row * 64 + col);
        bf[2 * ng][0] = t[0]; bf[2 * ng][1] = t[1];
        bf[2 * ng + 1][0] = t[2]; bf[2 * ng + 1][1] = t[3];
    }
}

__global__ __launch_bounds__(128, 3) void k_gemm(float* __restrict__ D) {
    extern __shared__ char smem[];
    const uint32_t sb = smem_u32(smem);
    const int tid = threadIdx.x, wid = tid >> 5, lane = tid & 31;
    const int n0 = blockIdx.x << 7, m0 = blockIdx.y << 7;
    const int wm = (wid >> 1) << 6;
    const int wn = (wid & 1) << 6;

    load_chunk(sb + 0 * STG_BYTES, sb + 0 * STG_BYTES + T_BYTES, m0, n0, 0 * KC, tid);
    load_chunk(sb + 1 * STG_BYTES, sb + 1 * STG_BYTES + T_BYTES, m0, n0, 1 * KC, tid);
    load_chunk(sb + 2 * STG_BYTES, sb + 2 * STG_BYTES + T_BYTES, m0, n0, 2 * KC, tid);

    uint32_t acc[4][8][2];
    #pragma unroll
    for (int im = 0; im < 4; im++)
        #pragma unroll
        for (int jn = 0; jn < 8; jn++) { acc[im][jn][0] = 0u; acc[im][jn][1] = 0u; }

    const int a_row = wm + (lane & 15);
    const int a_hi  = lane >> 4;
    const int b_row = wn + (lane & 7) + (((lane >> 4) & 1) << 3);
    const int b_hi  = (lane >> 3) & 1;

    uint32_t af[2][4][4], bf[2][8][2];

    #pragma unroll 1
    for (int i = 0; i < NCHUNK; i++) {
        if (i <= NCHUNK - 3)      asm volatile("cp.async.wait_group 2;" ::: "memory");
        else if (i == NCHUNK - 2) asm volatile("cp.async.wait_group 1;" ::: "memory");
        else                      asm volatile("cp.async.wait_group 0;" ::: "memory");
        __syncthreads();
        if (i + 3 < NCHUNK)
            load_chunk(sb + ((i + 3) & 3) * STG_BYTES,
                       sb + ((i + 3) & 3) * STG_BYTES + T_BYTES, m0, n0, (i + 3) * KC, tid);
        const uint32_t abase = sb + (i & 3) * STG_BYTES;
        const uint32_t bbase = abase + T_BYTES;
        load_frags(abase, bbase, 0, af[0], bf[0], a_row, a_hi, b_row, b_hi);
        #pragma unroll
        for (int ks = 0; ks < 2; ks++) {
            if (ks < 1)
                load_frags(abase, bbase, 1, af[1], bf[1], a_row, a_hi, b_row, b_hi);
            #pragma unroll
            for (int im = 0; im < 4; im++)
                #pragma unroll
                for (int jn = 0; jn < 8; jn++)
                    mma16816h(acc[im][jn], af[ks & 1][im], bf[ks & 1][jn]);
        }
    }

    const int g = lane >> 2, tig = lane & 3;
    float* dbase = D + (size_t)(m0 + wm + g) * NCODE + n0 + wn + tig * 2;
    #pragma unroll
    for (int im = 0; im < 4; im++) {
        #pragma unroll
        for (int jn = 0; jn < 8; jn++) {
            float* p = dbase + (size_t)(im * 16) * NCODE + jn * 8;
            *(float2*)p = __half22float2(*(__half2*)&acc[im][jn][0]);
            *(float2*)(p + (size_t)8 * NCODE) = __half22float2(*(__half2*)&acc[im][jn][1]);
        }
    }

    #pragma unroll
    for (int im = 0; im < 4; im++) {
        #pragma unroll
        for (int h = 0; h < 2; h++) {
            __half2 m = *(__half2*)&acc[im][0][h];
            #pragma unroll
            for (int jn = 1; jn < 8; jn++) m = __hmax2(m, *(__half2*)&acc[im][jn][h]);
            float2 f = __half22float2(m);
            float v = fmaxf(f.x, f.y);
            v = fmaxf(v, __shfl_xor_sync(0xffffffffu, v, 1));
            v = fmaxf(v, __shfl_xor_sync(0xffffffffu, v, 2));
            if (tig == 0)
                atomicMax(&g_tmax[(size_t)(m0 + wm + im * 16 + h * 8 + g) * NTILES + blockIdx.x],
                          fmap(v));
        }
    }
}

// ---------------- refine: one warp per row ----------------
#define MAXC 32
__global__ __launch_bounds__(256) void k_refine(
    const float* __restrict__ dist, const float* __restrict__ x,
    const float* __restrict__ e, float* __restrict__ qout, float* __restrict__ iout) {
    const int warp = threadIdx.x >> 5, lane = threadIdx.x & 31;
    const int r = blockIdx.x * 8 + warp;

    const float t0 = funmap(g_tmax[(size_t)r * NTILES + lane]);
    const float t1 = funmap(g_tmax[(size_t)r * NTILES + 32 + lane]);
    float m = fmaxf(t0, t1);
    #pragma unroll
    for (int o = 16; o; o >>= 1) m = fmaxf(m, __shfl_xor_sync(0xffffffffu, m, o));
    const float thr = m - 0.008f;

    __shared__ int s_cols[8][MAXC];
    __shared__ int s_cnt[8];
    __shared__ double s_val[8][MAXC];
    __shared__ float s_inv[8][MAXC];
    if (lane == 0) s_cnt[warp] = 0;
    __syncwarp();

    const float* drow = dist + (size_t)r * NCODE;
    for (int t = 0; t < NTILES; t++) {
        float tm = __shfl_sync(0xffffffffu, (t < 32) ? t0 : t1, t & 31);
        if (tm >= thr) {
            float4 v = ((const float4*)(drow + t * NTILE))[lane];
            int c0 = t * NTILE + lane * 4;
            if (v.x >= thr) { int p = atomicAdd(&s_cnt[warp], 1); if (p < MAXC) s_cols[warp][p] = c0; }
            if (v.y >= thr) { int p = atomicAdd(&s_cnt[warp], 1); if (p < MAXC) s_cols[warp][p] = c0 + 1; }
            if (v.z >= thr) { int p = atomicAdd(&s_cnt[warp], 1); if (p < MAXC) s_cols[warp][p] = c0 + 2; }
            if (v.w >= thr) { int p = atomicAdd(&s_cnt[warp], 1); if (p < MAXC) s_cols[warp][p] = c0 + 3; }
        }
    }
    __syncwarp();
    const int nc = min(s_cnt[warp], MAXC);

    const float* xr = x + (size_t)r * DDIM;
    for (int cI = 0; cI < nc; cI++) {
        const float* er = e + (size_t)s_cols[warp][cI] * DDIM;
        float s = 0.f, comp = 0.f, es = 0.f, ecomp = 0.f;
        #pragma unroll
        for (int k = lane; k < DDIM; k += 32) {
            float a = xr[k], b = er[k];
            float p = __fmul_rn(a, b);
            float pe = __fmaf_rn(a, b, -p);
            float t = __fadd_rn(s, p);
            float z = __fsub_rn(t, s);
            comp = __fadd_rn(comp, __fadd_rn(__fsub_rn(s, __fsub_rn(t, z)), __fsub_rn(p, z)));
            s = t; comp = __fadd_rn(comp, pe);
            float q2 = __fmul_rn(b, b);
            float qe = __fmaf_rn(b, b, -q2);
            float t2 = __fadd_rn(es, q2);
            float z2 = __fsub_rn(t2, es);
            ecomp = __fadd_rn(ecomp, __fadd_rn(__fsub_rn(es, __fsub_rn(t2, z2)), __fsub_rn(q2, z2)));
            es = t2; ecomp = __fadd_rn(ecomp, qe);
        }
        double ds = (double)s + (double)comp;
        double de = (double)es + (double)ecomp;
        #pragma unroll
        for (int o = 16; o; o >>= 1) {
            ds += __shfl_down_sync(0xffffffffu, ds, o);
            de += __shfl_down_sync(0xffffffffu, de, o);
        }
        if (lane == 0) {
            double ne = sqrt(de);
            s_val[warp][cI] = ds / ne;
            s_inv[warp][cI] = (float)(1.0 / (ne > 1e-12 ? ne : 1e-12));
        }
    }
    __syncwarp();

    int bc = 0; float bi = 0.f;
    if (lane == 0) {
        double best = -1e300; bc = 0x7fffffff;
        for (int c = 0; c < nc; c++) {
            double v = s_val[warp][c]; int col = s_cols[warp][c];
            if (v > best || (v == best && col < bc)) { best = v; bc = col; bi = s_inv[warp][c]; }
        }
        iout[r] = (float)bc;
    }
    bc = __shfl_sync(0xffffffffu, bc, 0);
    bi = __shfl_sync(0xffffffffu, bi, 0);

    const float4* ew = (const float4*)(e + (size_t)bc * DDIM);
    float4* qo = (float4*)(qout + (size_t)r * DDIM);
    #pragma unroll
    for (int q = lane; q < DDIM / 4; q += 32) {
        float4 v = ew[q];
        qo[q] = make_float4(v.x * bi, v.y * bi, v.z * bi, v.w * bi);
    }
}

// ---------------- launch ----------------
extern "C" void kernel_launch(void* const* d_in, const int* in_sizes, int n_in,
                              void* d_out, int out_size) {
    (void)in_sizes; (void)n_in; (void)out_size;
    const float* x = (const float*)d_in[0];
    const float* e = (const float*)d_in[1];
    float* qout = (float*)d_out;
    float* iout = qout + (size_t)NROWS * DDIM;
    float* dist = iout + NROWS;

    cudaFuncSetAttribute(k_gemm, cudaFuncAttributeMaxDynamicSharedMemorySize, GEMM_SMEM);
    k_norm<<<NROWS + NCODE, 128>>>(x, e);
    dim3 gg(NCODE / 128, NROWS / 128);
    k_gemm<<<gg, 128, GEMM_SMEM>>>(dist);
    k_refine<<<NROWS / 8, 256>>>(dist, x, e, qout, iout);
}

// round 16
// speedup vs baseline: 1.1026x; 1.1026x over previous
#include <cuda_runtime.h>
#include <cuda_fp16.h>
#include <cstdint>

#define NROWS 16384
#define NCODE 8192
#define DDIM  512
#define NTILE 128
#define NTILES (NCODE / NTILE)   /* 64 */

__device__ __half g_xh[(size_t)NROWS * DDIM];
__device__ __half g_eh[(size_t)NCODE * DDIM];
__device__ unsigned g_tmax[(size_t)NROWS * NTILES];   // order-mapped floats; 0 = identity

// ---------------- helpers ----------------
static __device__ __forceinline__ uint32_t smem_u32(const void* p) {
    uint32_t a;
    asm("{ .reg .u64 t; cvta.to.shared.u64 t, %1; cvt.u32.u64 %0, t; }" : "=r"(a) : "l"(p));
    return a;
}
static __device__ __forceinline__ void cp16(uint32_t dst, const void* src) {
    asm volatile("cp.async.cg.shared.global [%0], [%1], 16;"
                 :: "r"(dst), "l"(__cvta_generic_to_global(src)));
}
static __device__ __forceinline__ void ldsm_x4(uint32_t* r, uint32_t addr) {
    asm volatile("ldmatrix.sync.aligned.m8n8.x4.shared.b16 {%0,%1,%2,%3}, [%4];"
                 : "=r"(r[0]), "=r"(r[1]), "=r"(r[2]), "=r"(r[3]) : "r"(addr));
}
static __device__ __forceinline__ void mma16816h(uint32_t* d, const uint32_t* a, const uint32_t* b) {
    asm volatile(
        "mma.sync.aligned.m16n8k16.row.col.f16.f16.f16.f16 "
        "{%0,%1},{%2,%3,%4,%5},{%6,%7},{%0,%1};"
        : "+r"(d[0]), "+r"(d[1])
        : "r"(a[0]), "r"(a[1]), "r"(a[2]), "r"(a[3]), "r"(b[0]), "r"(b[1]));
}
static __device__ __forceinline__ unsigned fmap(float v) {
    int i = __float_as_int(v);
    return (unsigned)i ^ (unsigned)((i >> 31) | 0x80000000);
}
static __device__ __forceinline__ float funmap(unsigned k) {
    int i = (k & 0x80000000u) ? (int)(k ^ 0x80000000u) : (int)~k;
    return __int_as_float(i);
}

// ---------------- normalize rows -> f16 (+ clear g_tmax) ----------------
__global__ __launch_bounds__(128) void k_norm(const float* __restrict__ x,
                                              const float* __restrict__ e) {
    const int b = blockIdx.x, tid = threadIdx.x;
    const float* in;
    __half* out;
    if (b < NROWS) {
        in = x + (size_t)b * DDIM; out = g_xh + (size_t)b * DDIM;
        if (tid < NTILES) g_tmax[(size_t)b * NTILES + tid] = 0u;
    } else {
        in = e + (size_t)(b - NROWS) * DDIM; out = g_eh + (size_t)(b - NROWS) * DDIM;
    }
    const float4 v = ((const float4*)in)[tid];
    float ss = v.x * v.x + v.y * v.y + v.z * v.z + v.w * v.w;
    #pragma unroll
    for (int o = 16; o; o >>= 1) ss += __shfl_down_sync(0xffffffffu, ss, o);
    __shared__ float sred[4];
    if ((tid & 31) == 0) sred[tid >> 5] = ss;
    __syncthreads();
    if (tid == 0) {
        float t = sred[0] + sred[1] + sred[2] + sred[3];
        sred[0] = 1.0f / fmaxf(sqrtf(t), 1e-12f);
    }
    __syncthreads();
    const float sc = sred[0];
    __half2* oh = (__half2*)out;
    oh[tid * 2]     = __floats2half2_rn(v.x * sc, v.y * sc);
    oh[tid * 2 + 1] = __floats2half2_rn(v.z * sc, v.w * sc);
}

// ---------------- mma.sync GEMM (f16 acc): CTA 256x128, 8 warps 64x64 ------
// KC=64 (128-B rows, 3-bit swizzle), 2 stages (96 KB), 2 CTAs/SM ->
// 4 warps/SMSP. Halves L2 operand traffic vs 128x128 CTA.
#define A_BYTES (256 * 128)             /* 32 KB */
#define B_BYTES (128 * 128)             /* 16 KB */
#define STG_BYTES (A_BYTES + B_BYTES)   /* 48 KB */
#define GEMM_SMEM (2 * STG_BYTES)       /* 96 KB */

static __device__ __forceinline__ void load_chunk(uint32_t abase, uint32_t bbase,
                                                  int m0, int n0, int k0, int tid) {
    #pragma unroll
    for (int i = 0; i < 8; i++) {       // A: 256 rows x 8 groups
        int idx = tid + (i << 8);
        int row = idx >> 3, g = idx & 7;
        uint32_t dst = (uint32_t)(row * 128) + ((uint32_t)(g ^ (row & 7)) << 4);
        cp16(abase + dst, g_xh + (size_t)(m0 + row) * DDIM + k0 + g * 8);
    }
    #pragma unroll
    for (int i = 0; i < 4; i++) {       // B: 128 rows x 8 groups
        int idx = tid + (i << 8);
        int row = idx >> 3, g = idx & 7;
        uint32_t dst = (uint32_t)(row * 128) + ((uint32_t)(g ^ (row & 7)) << 4);
        cp16(bbase + dst, g_eh + (size_t)(n0 + row) * DDIM + k0 + g * 8);
    }
    asm volatile("cp.async.commit_group;" ::: "memory");
}

__global__ __launch_bounds__(256, 2) void k_gemm(float* __restrict__ D) {
    extern __shared__ char smem[];
    const uint32_t sb = smem_u32(smem);
    const int tid = threadIdx.x, wid = tid >> 5, lane = tid & 31;
    const int n0 = blockIdx.x << 7, m0 = blockIdx.y << 8;
    const int wm = (wid >> 1) << 6;       // 0,64,128,192
    const int wn = (wid & 1) << 6;        // 0 or 64

    load_chunk(sb, sb + A_BYTES, m0, n0, 0, tid);

    uint32_t acc[4][8][2];                // f16x2: 64 regs
    #pragma unroll
    for (int im = 0; im < 4; im++)
        #pragma unroll
        for (int jn = 0; jn < 8; jn++) { acc[im][jn][0] = 0u; acc[im][jn][1] = 0u; }

    const int a_row = wm + (lane & 15);
    const int a_hi  = lane >> 4;
    const int b_row = wn + (lane & 7) + (((lane >> 4) & 1) << 3);
    const int b_hi  = (lane >> 3) & 1;

    #pragma unroll 1
    for (int i = 0; i < 8; i++) {
        asm volatile("cp.async.wait_group 0;" ::: "memory");
        __syncthreads();
        if (i + 1 < 8)
            load_chunk(sb + ((i + 1) & 1) * STG_BYTES,
                       sb + ((i + 1) & 1) * STG_BYTES + A_BYTES, m0, n0, (i + 1) * 64, tid);
        const uint32_t abase = sb + (i & 1) * STG_BYTES;
        const uint32_t bbase = abase + A_BYTES;
        #pragma unroll
        for (int ks = 0; ks < 4; ks++) {
            uint32_t af[4][4], bf[8][2];
            #pragma unroll
            for (int im = 0; im < 4; im++) {
                int row = a_row + im * 16;
                uint32_t col = (uint32_t)((ks * 2 + a_hi) ^ (row & 7)) << 4;
                ldsm_x4(af[im], abase + row * 128 + col);
            }
            #pragma unroll
            for (int ng = 0; ng < 4; ng++) {
                int row = b_row + ng * 16;
                uint32_t col = (uint32_t)((ks * 2 + b_hi) ^ (row & 7)) << 4;
                uint32_t t[4];
                ldsm_x4(t, bbase + row * 128 + col);
                bf[2 * ng][0] = t[0]; bf[2 * ng][1] = t[1];
                bf[2 * ng + 1][0] = t[2]; bf[2 * ng + 1][1] = t[3];
            }
            #pragma unroll
            for (int im = 0; im < 4; im++)
                #pragma unroll
                for (int jn = 0; jn < 8; jn++)
                    mma16816h(acc[im][jn], af[im], bf[jn]);
        }
    }

    // ---- dist stores ----
    const int g = lane >> 2, tig = lane & 3;
    float* dbase = D + (size_t)(m0 + wm + g) * NCODE + n0 + wn + tig * 2;
    #pragma unroll
    for (int im = 0; im < 4; im++) {
        #pragma unroll
        for (int jn = 0; jn < 8; jn++) {
            float* p = dbase + (size_t)(im * 16) * NCODE + jn * 8;
            *(float2*)p = __half22float2(*(__half2*)&acc[im][jn][0]);
            *(float2*)(p + (size_t)8 * NCODE) = __half22float2(*(__half2*)&acc[im][jn][1]);
        }
    }

    // ---- tmax via RED.MAX (no smem, no syncs) ----
    #pragma unroll
    for (int im = 0; im < 4; im++) {
        #pragma unroll
        for (int h = 0; h < 2; h++) {
            __half2 m = *(__half2*)&acc[im][0][h];
            #pragma unroll
            for (int jn = 1; jn < 8; jn++) m = __hmax2(m, *(__half2*)&acc[im][jn][h]);
            float2 f = __half22float2(m);
            float v = fmaxf(f.x, f.y);
            v = fmaxf(v, __shfl_xor_sync(0xffffffffu, v, 1));
            v = fmaxf(v, __shfl_xor_sync(0xffffffffu, v, 2));
            if (tig == 0)
                atomicMax(&g_tmax[(size_t)(m0 + wm + im * 16 + h * 8 + g) * NTILES + blockIdx.x],
                          fmap(v));
        }
    }
}

// ---------------- refine: one warp per row ----------------
#define MAXC 32
__global__ __launch_bounds__(256) void k_refine(
    const float* __restrict__ dist, const float* __restrict__ x,
    const float* __restrict__ e, float* __restrict__ qout, float* __restrict__ iout) {
    const int warp = threadIdx.x >> 5, lane = threadIdx.x & 31;
    const int r = blockIdx.x * 8 + warp;

    const float t0 = funmap(g_tmax[(size_t)r * NTILES + lane]);
    const float t1 = funmap(g_tmax[(size_t)r * NTILES + 32 + lane]);
    float m = fmaxf(t0, t1);
    #pragma unroll
    for (int o = 16; o; o >>= 1) m = fmaxf(m, __shfl_xor_sync(0xffffffffu, m, o));
    const float thr = m - 0.008f;

    __shared__ int s_cols[8][MAXC];
    __shared__ int s_cnt[8];
    __shared__ double s_val[8][MAXC];
    __shared__ float s_inv[8][MAXC];
    if (lane == 0) s_cnt[warp] = 0;
    __syncwarp();

    const float* drow = dist + (size_t)r * NCODE;
    for (int t = 0; t < NTILES; t++) {
        float tm = __shfl_sync(0xffffffffu, (t < 32) ? t0 : t1, t & 31);
        if (tm >= thr) {
            float4 v = ((const float4*)(drow + t * NTILE))[lane];
            int c0 = t * NTILE + lane * 4;
            if (v.x >= thr) { int p = atomicAdd(&s_cnt[warp], 1); if (p < MAXC) s_cols[warp][p] = c0; }
            if (v.y >= thr) { int p = atomicAdd(&s_cnt[warp], 1); if (p < MAXC) s_cols[warp][p] = c0 + 1; }
            if (v.z >= thr) { int p = atomicAdd(&s_cnt[warp], 1); if (p < MAXC) s_cols[warp][p] = c0 + 2; }
            if (v.w >= thr) { int p = atomicAdd(&s_cnt[warp], 1); if (p < MAXC) s_cols[warp][p] = c0 + 3; }
        }
    }
    __syncwarp();
    const int nc = min(s_cnt[warp], MAXC);

    const float* xr = x + (size_t)r * DDIM;
    for (int cI = 0; cI < nc; cI++) {
        const float* er = e + (size_t)s_cols[warp][cI] * DDIM;
        float s = 0.f, comp = 0.f, es = 0.f, ecomp = 0.f;
        #pragma unroll
        for (int k = lane; k < DDIM; k += 32) {
            float a = xr[k], b = er[k];
            float p = __fmul_rn(a, b);
            float pe = __fmaf_rn(a, b, -p);
            float t = __fadd_rn(s, p);
            float z = __fsub_rn(t, s);
            comp = __fadd_rn(comp, __fadd_rn(__fsub_rn(s, __fsub_rn(t, z)), __fsub_rn(p, z)));
            s = t; comp = __fadd_rn(comp, pe);
            float q2 = __fmul_rn(b, b);
            float qe = __fmaf_rn(b, b, -q2);
            float t2 = __fadd_rn(es, q2);
            float z2 = __fsub_rn(t2, es);
            ecomp = __fadd_rn(ecomp, __fadd_rn(__fsub_rn(es, __fsub_rn(t2, z2)), __fsub_rn(q2, z2)));
            es = t2; ecomp = __fadd_rn(ecomp, qe);
        }
        double ds = (double)s + (double)comp;
        double de = (double)es + (double)ecomp;
        #pragma unroll
        for (int o = 16; o; o >>= 1) {
            ds += __shfl_down_sync(0xffffffffu, ds, o);
            de += __shfl_down_sync(0xffffffffu, de, o);
        }
        if (lane == 0) {
            double ne = sqrt(de);
            s_val[warp][cI] = ds / ne;
            s_inv[warp][cI] = (float)(1.0 / (ne > 1e-12 ? ne : 1e-12));
        }
    }
    __syncwarp();

    int bc = 0; float bi = 0.f;
    if (lane == 0) {
        double best = -1e300; bc = 0x7fffffff;
        for (int c = 0; c < nc; c++) {
            double v = s_val[warp][c]; int col = s_cols[warp][c];
            if (v > best || (v == best && col < bc)) { best = v; bc = col; bi = s_inv[warp][c]; }
        }
        iout[r] = (float)bc;
    }
    bc = __shfl_sync(0xffffffffu, bc, 0);
    bi = __shfl_sync(0xffffffffu, bi, 0);

    const float4* ew = (const float4*)(e + (size_t)bc * DDIM);
    float4* qo = (float4*)(qout + (size_t)r * DDIM);
    #pragma unroll
    for (int q = lane; q < DDIM / 4; q += 32) {
        float4 v = ew[q];
        qo[q] = make_float4(v.x * bi, v.y * bi, v.z * bi, v.w * bi);
    }
}

// ---------------- launch ----------------
extern "C" void kernel_launch(void* const* d_in, const int* in_sizes, int n_in,
                              void* d_out, int out_size) {
    (void)in_sizes; (void)n_in; (void)out_size;
    const float* x = (const float*)d_in[0];
    const float* e = (const float*)d_in[1];
    float* qout = (float*)d_out;
    float* iout = qout + (size_t)NROWS * DDIM;
    float* dist = iout + NROWS;

    cudaFuncSetAttribute(k_gemm, cudaFuncAttributeMaxDynamicSharedMemorySize, GEMM_SMEM);
    k_norm<<<NROWS + NCODE, 128>>>(x, e);
    dim3 gg(NCODE / 128, NROWS / 256);
    k_gemm<<<gg, 256, GEMM_SMEM>>>(dist);
    k_refine<<<NROWS / 8, 256>>>(dist, x, e, qout, iout);
}

// round 17
// speedup vs baseline: 1.1473x; 1.0406x over previous
#include <cuda_runtime.h>
#include <cuda_fp16.h>
#include <cstdint>

#define NROWS 16384
#define NCODE 8192
#define DDIM  512
#define NTILE 128
#define NTILES (NCODE / NTILE)   /* 64 */

__device__ __half g_xh[(size_t)NROWS * DDIM];
__device__ __half g_eh[(size_t)NCODE * DDIM];
__device__ unsigned g_tmax[(size_t)NROWS * NTILES];   // order-mapped floats; 0 = identity

// ---------------- helpers ----------------
static __device__ __forceinline__ uint32_t smem_u32(const void* p) {
    uint32_t a;
    asm("{ .reg .u64 t; cvta.to.shared.u64 t, %1; cvt.u32.u64 %0, t; }" : "=r"(a) : "l"(p));
    return a;
}
static __device__ __forceinline__ void cp16(uint32_t dst, const void* src) {
    asm volatile("cp.async.cg.shared.global [%0], [%1], 16;"
                 :: "r"(dst), "l"(__cvta_generic_to_global(src)));
}
static __device__ __forceinline__ void ldsm_x4(uint32_t* r, uint32_t addr) {
    asm volatile("ldmatrix.sync.aligned.m8n8.x4.shared.b16 {%0,%1,%2,%3}, [%4];"
                 : "=r"(r[0]), "=r"(r[1]), "=r"(r[2]), "=r"(r[3]) : "r"(addr));
}
static __device__ __forceinline__ void mma16816h(uint32_t* d, const uint32_t* a, const uint32_t* b) {
    asm volatile(
        "mma.sync.aligned.m16n8k16.row.col.f16.f16.f16.f16 "
        "{%0,%1},{%2,%3,%4,%5},{%6,%7},{%0,%1};"
        : "+r"(d[0]), "+r"(d[1])
        : "r"(a[0]), "r"(a[1]), "r"(a[2]), "r"(a[3]), "r"(b[0]), "r"(b[1]));
}
static __device__ __forceinline__ unsigned fmap(float v) {
    int i = __float_as_int(v);
    return (unsigned)i ^ (unsigned)((i >> 31) | 0x80000000);
}
static __device__ __forceinline__ float funmap(unsigned k) {
    int i = (k & 0x80000000u) ? (int)(k ^ 0x80000000u) : (int)~k;
    return __int_as_float(i);
}

// ---------------- normalize rows -> f16 (+ clear g_tmax) ----------------
__global__ __launch_bounds__(128) void k_norm(const float* __restrict__ x,
                                              const float* __restrict__ e) {
    const int b = blockIdx.x, tid = threadIdx.x;
    const float* in;
    __half* out;
    if (b < NROWS) {
        in = x + (size_t)b * DDIM; out = g_xh + (size_t)b * DDIM;
        if (tid < NTILES) g_tmax[(size_t)b * NTILES + tid] = 0u;
    } else {
        in = e + (size_t)(b - NROWS) * DDIM; out = g_eh + (size_t)(b - NROWS) * DDIM;
    }
    const float4 v = ((const float4*)in)[tid];
    float ss = v.x * v.x + v.y * v.y + v.z * v.z + v.w * v.w;
    #pragma unroll
    for (int o = 16; o; o >>= 1) ss += __shfl_down_sync(0xffffffffu, ss, o);
    __shared__ float sred[4];
    if ((tid & 31) == 0) sred[tid >> 5] = ss;
    __syncthreads();
    if (tid == 0) {
        float t = sred[0] + sred[1] + sred[2] + sred[3];
        sred[0] = 1.0f / fmaxf(sqrtf(t), 1e-12f);
    }
    __syncthreads();
    const float sc = sred[0];
    __half2* oh = (__half2*)out;
    oh[tid * 2]     = __floats2half2_rn(v.x * sc, v.y * sc);
    oh[tid * 2 + 1] = __floats2half2_rn(v.z * sc, v.w * sc);
}

// ---------------- mma.sync GEMM (f16 acc): R13 + interleaved prefetch ------
// CTA 128x128, 128 threads (2x2 warps, warp 64x64), KC=64 (128-B rows),
// 2 stages (64 KB), 3 CTAs/SM, reg-dbuf fragments. Prefetch of chunk i+1 is
// issued in 4 parts across the ks loop to smooth LSU pressure.
#define T_BYTES (128 * 128)
#define STG_BYTES (2 * T_BYTES)
#define GEMM_SMEM (2 * STG_BYTES)       /* 64 KB */

static __device__ __forceinline__ void load_part(uint32_t abase, uint32_t bbase,
                                                 int m0, int n0, int k0, int part, int tid) {
    #pragma unroll
    for (int j = 0; j < 2; j++) {
        int i = part * 2 + j;
        int idx = tid + (i << 7);
        int row = idx >> 3, g = idx & 7;
        uint32_t dst = (uint32_t)(row * 128) + ((uint32_t)(g ^ (row & 7)) << 4);
        cp16(abase + dst, g_xh + (size_t)(m0 + row) * DDIM + k0 + g * 8);
        cp16(bbase + dst, g_eh + (size_t)(n0 + row) * DDIM + k0 + g * 8);
    }
}

static __device__ __forceinline__ void load_frags(
    uint32_t abase, uint32_t bbase, int ks,
    uint32_t af[4][4], uint32_t bf[8][2],
    int a_row, int a_hi, int b_row, int b_hi) {
    #pragma unroll
    for (int im = 0; im < 4; im++) {
        int row = a_row + im * 16;
        uint32_t col = (uint32_t)((ks * 2 + a_hi) ^ (row & 7)) << 4;
        ldsm_x4(af[im], abase + row * 128 + col);
    }
    #pragma unroll
    for (int ng = 0; ng < 4; ng++) {
        int row = b_row + ng * 16;
        uint32_t col = (uint32_t)((ks * 2 + b_hi) ^ (row & 7)) << 4;
        uint32_t t[4];
        ldsm_x4(t, bbase + row * 128 + col);
        bf[2 * ng][0] = t[0]; bf[2 * ng][1] = t[1];
        bf[2 * ng + 1][0] = t[2]; bf[2 * ng + 1][1] = t[3];
    }
}

__global__ __launch_bounds__(128, 3) void k_gemm(float* __restrict__ D) {
    extern __shared__ char smem[];
    const uint32_t sb = smem_u32(smem);
    const int tid = threadIdx.x, wid = tid >> 5, lane = tid & 31;
    const int n0 = blockIdx.x << 7, m0 = blockIdx.y << 7;
    const int wm = (wid >> 1) << 6;
    const int wn = (wid & 1) << 6;

    // prologue: chunk 0 in one burst
    #pragma unroll
    for (int p = 0; p < 4; p++)
        load_part(sb, sb + T_BYTES, m0, n0, 0, p, tid);
    asm volatile("cp.async.commit_group;" ::: "memory");

    uint32_t acc[4][8][2];
    #pragma unroll
    for (int im = 0; im < 4; im++)
        #pragma unroll
        for (int jn = 0; jn < 8; jn++) { acc[im][jn][0] = 0u; acc[im][jn][1] = 0u; }

    const int a_row = wm + (lane & 15);
    const int a_hi  = lane >> 4;
    const int b_row = wn + (lane & 7) + (((lane >> 4) & 1) << 3);
    const int b_hi  = (lane >> 3) & 1;

    uint32_t af[2][4][4], bf[2][8][2];

    #pragma unroll 1
    for (int i = 0; i < 8; i++) {
        asm volatile("cp.async.wait_group 0;" ::: "memory");
        __syncthreads();
        const uint32_t abase = sb + (i & 1) * STG_BYTES;
        const uint32_t bbase = abase + T_BYTES;
        const uint32_t nbase = sb + ((i + 1) & 1) * STG_BYTES;
        const bool pf = (i + 1 < 8);

        load_frags(abase, bbase, 0, af[0], bf[0], a_row, a_hi, b_row, b_hi);
        #pragma unroll
        for (int ks = 0; ks < 4; ks++) {
            if (pf) load_part(nbase, nbase + T_BYTES, m0, n0, (i + 1) * 64, ks, tid);
            if (ks < 3)
                load_frags(abase, bbase, ks + 1, af[(ks + 1) & 1], bf[(ks + 1) & 1],
                           a_row, a_hi, b_row, b_hi);
            #pragma unroll
            for (int im = 0; im < 4; im++)
                #pragma unroll
                for (int jn = 0; jn < 8; jn++)
                    mma16816h(acc[im][jn], af[ks & 1][im], bf[ks & 1][jn]);
        }
        if (pf) asm volatile("cp.async.commit_group;" ::: "memory");
    }

    // ---- dist stores ----
    const int g = lane >> 2, tig = lane & 3;
    float* dbase = D + (size_t)(m0 + wm + g) * NCODE + n0 + wn + tig * 2;
    #pragma unroll
    for (int im = 0; im < 4; im++) {
        #pragma unroll
        for (int jn = 0; jn < 8; jn++) {
            float* p = dbase + (size_t)(im * 16) * NCODE + jn * 8;
            *(float2*)p = __half22float2(*(__half2*)&acc[im][jn][0]);
            *(float2*)(p + (size_t)8 * NCODE) = __half22float2(*(__half2*)&acc[im][jn][1]);
        }
    }

    // ---- tmax via RED.MAX ----
    #pragma unroll
    for (int im = 0; im < 4; im++) {
        #pragma unroll
        for (int h = 0; h < 2; h++) {
            __half2 m = *(__half2*)&acc[im][0][h];
            #pragma unroll
            for (int jn = 1; jn < 8; jn++) m = __hmax2(m, *(__half2*)&acc[im][jn][h]);
            float2 f = __half22float2(m);
            float v = fmaxf(f.x, f.y);
            v = fmaxf(v, __shfl_xor_sync(0xffffffffu, v, 1));
            v = fmaxf(v, __shfl_xor_sync(0xffffffffu, v, 2));
            if (tig == 0)
                atomicMax(&g_tmax[(size_t)(m0 + wm + im * 16 + h * 8 + g) * NTILES + blockIdx.x],
                          fmap(v));
        }
    }
}

// ---------------- refine: one warp per row ----------------
#define MAXC 32
__global__ __launch_bounds__(256) void k_refine(
    const float* __restrict__ dist, const float* __restrict__ x,
    const float* __restrict__ e, float* __restrict__ qout, float* __restrict__ iout) {
    const int warp = threadIdx.x >> 5, lane = threadIdx.x & 31;
    const int r = blockIdx.x * 8 + warp;

    const float t0 = funmap(g_tmax[(size_t)r * NTILES + lane]);
    const float t1 = funmap(g_tmax[(size_t)r * NTILES + 32 + lane]);
    float m = fmaxf(t0, t1);
    #pragma unroll
    for (int o = 16; o; o >>= 1) m = fmaxf(m, __shfl_xor_sync(0xffffffffu, m, o));
    const float thr = m - 0.008f;

    __shared__ int s_cols[8][MAXC];
    __shared__ int s_cnt[8];
    __shared__ double s_val[8][MAXC];
    __shared__ float s_inv[8][MAXC];
    if (lane == 0) s_cnt[warp] = 0;
    __syncwarp();

    const float* drow = dist + (size_t)r * NCODE;
    for (int t = 0; t < NTILES; t++) {
        float tm = __shfl_sync(0xffffffffu, (t < 32) ? t0 : t1, t & 31);
        if (tm >= thr) {
            float4 v = ((const float4*)(drow + t * NTILE))[lane];
            int c0 = t * NTILE + lane * 4;
            if (v.x >= thr) { int p = atomicAdd(&s_cnt[warp], 1); if (p < MAXC) s_cols[warp][p] = c0; }
            if (v.y >= thr) { int p = atomicAdd(&s_cnt[warp], 1); if (p < MAXC) s_cols[warp][p] = c0 + 1; }
            if (v.z >= thr) { int p = atomicAdd(&s_cnt[warp], 1); if (p < MAXC) s_cols[warp][p] = c0 + 2; }
            if (v.w >= thr) { int p = atomicAdd(&s_cnt[warp], 1); if (p < MAXC) s_cols[warp][p] = c0 + 3; }
        }
    }
    __syncwarp();
    const int nc = min(s_cnt[warp], MAXC);

    const float* xr = x + (size_t)r * DDIM;
    for (int cI = 0; cI < nc; cI++) {
        const float* er = e + (size_t)s_cols[warp][cI] * DDIM;
        float s = 0.f, comp = 0.f, es = 0.f, ecomp = 0.f;
        #pragma unroll
        for (int k = lane; k < DDIM; k += 32) {
            float a = xr[k], b = er[k];
            float p = __fmul_rn(a, b);
            float pe = __fmaf_rn(a, b, -p);
            float t = __fadd_rn(s, p);
            float z = __fsub_rn(t, s);
            comp = __fadd_rn(comp, __fadd_rn(__fsub_rn(s, __fsub_rn(t, z)), __fsub_rn(p, z)));
            s = t; comp = __fadd_rn(comp, pe);
            float q2 = __fmul_rn(b, b);
            float qe = __fmaf_rn(b, b, -q2);
            float t2 = __fadd_rn(es, q2);
            float z2 = __fsub_rn(t2, es);
            ecomp = __fadd_rn(ecomp, __fadd_rn(__fsub_rn(es, __fsub_rn(t2, z2)), __fsub_rn(q2, z2)));
            es = t2; ecomp = __fadd_rn(ecomp, qe);
        }
        double ds = (double)s + (double)comp;
        double de = (double)es + (double)ecomp;
        #pragma unroll
        for (int o = 16; o; o >>= 1) {
            ds += __shfl_down_sync(0xffffffffu, ds, o);
            de += __shfl_down_sync(0xffffffffu, de, o);
        }
        if (lane == 0) {
            double ne = sqrt(de);
            s_val[warp][cI] = ds / ne;
            s_inv[warp][cI] = (float)(1.0 / (ne > 1e-12 ? ne : 1e-12));
        }
    }
    __syncwarp();

    int bc = 0; float bi = 0.f;
    if (lane == 0) {
        double best = -1e300; bc = 0x7fffffff;
        for (int c = 0; c < nc; c++) {
            double v = s_val[warp][c]; int col = s_cols[warp][c];
            if (v > best || (v == best && col < bc)) { best = v; bc = col; bi = s_inv[warp][c]; }
        }
        iout[r] = (float)bc;
    }
    bc = __shfl_sync(0xffffffffu, bc, 0);
    bi = __shfl_sync(0xffffffffu, bi, 0);

    const float4* ew = (const float4*)(e + (size_t)bc * DDIM);
    float4* qo = (float4*)(qout + (size_t)r * DDIM);
    #pragma unroll
    for (int q = lane; q < DDIM / 4; q += 32) {
        float4 v = ew[q];
        qo[q] = make_float4(v.x * bi, v.y * bi, v.z * bi, v.w * bi);
    }
}

// ---------------- launch ----------------
extern "C" void kernel_launch(void* const* d_in, const int* in_sizes, int n_in,
                              void* d_out, int out_size) {
    (void)in_sizes; (void)n_in; (void)out_size;
    const float* x = (const float*)d_in[0];
    const float* e = (const float*)d_in[1];
    float* qout = (float*)d_out;
    float* iout = qout + (size_t)NROWS * DDIM;
    float* dist = iout + NROWS;

    cudaFuncSetAttribute(k_gemm, cudaFuncAttributeMaxDynamicSharedMemorySize, GEMM_SMEM);
    k_norm<<<NROWS + NCODE, 128>>>(x, e);
    dim3 gg(NCODE / 128, NROWS / 128);
    k_gemm<<<gg, 128, GEMM_SMEM>>>(dist);
    k_refine<<<NROWS / 8, 256>>>(dist, x, e, qout, iout);
}